// round 3
// baseline (speedup 1.0000x reference)
#include <cuda_runtime.h>
#include <math.h>
#include <math_constants.h>

#define D_DIM 128
#define MAXN  50048
#define EPS_F 1e-8f
#define FULL  0xffffffffu

typedef unsigned long long u64;

// Scratch for the diag-scaled projection y = (x @ W^T) * sqrt(softplus(log_diag)+eps)
__device__ float g_xp[(size_t)MAXN * D_DIM];

// ---- packed fp32x2 helpers (Blackwell sm_100a) ------------------------------
__device__ __forceinline__ u64 pk2(float lo, float hi) {
    u64 r; asm("mov.b64 %0, {%1, %2};" : "=l"(r) : "f"(lo), "f"(hi)); return r;
}
__device__ __forceinline__ void upk2(u64 v, float& lo, float& hi) {
    asm("mov.b64 {%0, %1}, %2;" : "=f"(lo), "=f"(hi) : "l"(v));
}
__device__ __forceinline__ u64 fma2(u64 a, u64 b, u64 c) {
    u64 d; asm("fma.rn.f32x2 %0, %1, %2, %3;" : "=l"(d) : "l"(a), "l"(b), "l"(c));
    return d;
}

// ---------------------------------------------------------------------------
// Kernel 1: projection GEMM, 128x128 block tile, 8x8 register micro-tile,
// K tiled by 32. Inner product uses packed fma.rn.f32x2 (2 fp32 FMA / instr,
// bitwise-identical IEEE results). Accumulators paired over adjacent columns;
// W-tile float4 loads reinterpret directly as packed pairs (no pack cost).
// Epilogue folds sqrt(diag).
// ---------------------------------------------------------------------------
__global__ __launch_bounds__(256) void proj_kernel(
    const float* __restrict__ X, const float* __restrict__ W,
    const float* __restrict__ logd, int N)
{
    __shared__ float Xs[128 * 32];   // [r][k]
    __shared__ float Wt[32 * 132];   // [k][c] padded pitch (132 fl = 528B, 16B-mult)
    __shared__ float scale[128];

    const int tid  = threadIdx.x;
    const int row0 = blockIdx.x * 128;

    if (tid < 128) {
        float ld = logd[tid];
        float sp = (ld > 20.f) ? ld : log1pf(expf(ld));
        scale[tid] = sqrtf(sp + EPS_F);
    }

    u64 acc[8][4];                   // [row][col-pair]; pair = (2j, 2j+1)
#pragma unroll
    for (int i = 0; i < 8; i++)
#pragma unroll
        for (int j = 0; j < 4; j++) acc[i][j] = 0ull;

    const int tx = tid & 15;         // column group (8 cols)
    const int ty = tid >> 4;         // row group    (8 rows)
    const int lr = tid >> 3;
    const int lk = (tid & 7) * 4;

    for (int kt = 0; kt < 4; kt++) {
        __syncthreads();
#pragma unroll
        for (int it = 0; it < 4; it++) {
            int r  = lr + it * 32;
            int gr = row0 + r;
            float4 xv = make_float4(0.f, 0.f, 0.f, 0.f);
            if (gr < N) xv = *(const float4*)(X + (size_t)gr * D_DIM + kt * 32 + lk);
            *(float4*)(Xs + r * 32 + lk) = xv;
        }
#pragma unroll
        for (int it = 0; it < 4; it++) {
            int c = lr + it * 32;
            float4 wv = *(const float4*)(W + (size_t)c * D_DIM + kt * 32 + lk);
            Wt[(lk + 0) * 132 + c] = wv.x;
            Wt[(lk + 1) * 132 + c] = wv.y;
            Wt[(lk + 2) * 132 + c] = wv.z;
            Wt[(lk + 3) * 132 + c] = wv.w;
        }
        __syncthreads();

#pragma unroll
        for (int k0 = 0; k0 < 32; k0 += 4) {
            // x values for this thread's 8 rows, 4 k's each
            float4 xr4[8];
#pragma unroll
            for (int i = 0; i < 8; i++)
                xr4[i] = *(const float4*)(Xs + (ty * 8 + i) * 32 + k0);

#pragma unroll
            for (int kk = 0; kk < 4; kk++) {
                // W columns as native packed pairs (contiguous in smem)
                const u64* wp = (const u64*)(Wt + (k0 + kk) * 132 + tx * 8);
                u64 w0 = wp[0], w1 = wp[1], w2 = wp[2], w3 = wp[3];
#pragma unroll
                for (int i = 0; i < 8; i++) {
                    float xv = (kk == 0) ? xr4[i].x : (kk == 1) ? xr4[i].y
                             : (kk == 2) ? xr4[i].z : xr4[i].w;
                    u64 xp = pk2(xv, xv);
                    acc[i][0] = fma2(xp, w0, acc[i][0]);
                    acc[i][1] = fma2(xp, w1, acc[i][1]);
                    acc[i][2] = fma2(xp, w2, acc[i][2]);
                    acc[i][3] = fma2(xp, w3, acc[i][3]);
                }
            }
        }
    }

    // Epilogue: unpack, scale by sqrt(diag), store
#pragma unroll
    for (int i = 0; i < 8; i++) {
        int gr = row0 + ty * 8 + i;
        if (gr < N) {
#pragma unroll
            for (int jp = 0; jp < 4; jp += 2) {
                float a0, a1, a2, a3;
                upk2(acc[i][jp],     a0, a1);
                upk2(acc[i][jp + 1], a2, a3);
                float4 o;
                o.x = a0 * scale[tx * 8 + jp * 2 + 0];
                o.y = a1 * scale[tx * 8 + jp * 2 + 1];
                o.z = a2 * scale[tx * 8 + jp * 2 + 2];
                o.w = a3 * scale[tx * 8 + jp * 2 + 3];
                *(float4*)(g_xp + (size_t)gr * D_DIM + tx * 8 + jp * 2) = o;
            }
        }
    }
}

// ---------------------------------------------------------------------------
// Kernel 2: one warp per node (unchanged from R2 — near its L2 floor).
// ---------------------------------------------------------------------------
__global__ __launch_bounds__(256, 4) void edge_kernel(
    const int* __restrict__ eidx, const float* __restrict__ logt,
    float* __restrict__ out, int N, int deg, int topk)
{
    const int warp = blockIdx.x * (blockDim.x >> 5) + (threadIdx.x >> 5);
    const int lane = threadIdx.x & 31;
    if (warp >= N) return;
    const int i = warp;

    const int* colp = eidx + (size_t)N * deg + (size_t)i * deg;
    int mycol = (lane < 16) ? colp[lane] : 0;

    float4 yi = *(const float4*)(g_xp + (size_t)i * D_DIM + lane * 4);

    const float rtemp = expf(-logt[0]);

    float p[16];
#pragma unroll
    for (int g = 0; g < 2; g++) {
        float4 v[8];
#pragma unroll
        for (int n = 0; n < 8; n++) {
            int c = __shfl_sync(FULL, mycol, g * 8 + n);
            v[n] = *(const float4*)(g_xp + (size_t)c * D_DIM + lane * 4);
        }
#pragma unroll
        for (int n = 0; n < 8; n++) {
            float dx = yi.x - v[n].x;
            float dy = yi.y - v[n].y;
            float dz = yi.z - v[n].z;
            float dw = yi.w - v[n].w;
            p[g * 8 + n] = dx * dx + dy * dy + dz * dz + dw * dw;
        }
    }

    // Butterfly transpose-reduce
    {
        const bool b0 = lane & 1;
#pragma unroll
        for (int k = 0; k < 8; k++) {
            float send = b0 ? p[k] : p[k + 8];
            float recv = __shfl_xor_sync(FULL, send, 1);
            p[k] = (b0 ? p[k + 8] : p[k]) + recv;
        }
        const bool b1 = lane & 2;
#pragma unroll
        for (int k = 0; k < 4; k++) {
            float send = b1 ? p[k] : p[k + 4];
            float recv = __shfl_xor_sync(FULL, send, 2);
            p[k] = (b1 ? p[k + 4] : p[k]) + recv;
        }
        const bool b2 = lane & 4;
#pragma unroll
        for (int k = 0; k < 2; k++) {
            float send = b2 ? p[k] : p[k + 2];
            float recv = __shfl_xor_sync(FULL, send, 4);
            p[k] = (b2 ? p[k + 2] : p[k]) + recv;
        }
        const bool b3 = lane & 8;
        {
            float send = b3 ? p[0] : p[1];
            float recv = __shfl_xor_sync(FULL, send, 8);
            p[0] = (b3 ? p[1] : p[0]) + recv;
        }
        p[0] += __shfl_xor_sync(FULL, p[0], 16);
    }

    const int l4  = lane & 15;
    const int rev = ((l4 & 1) << 3) | ((l4 & 2) << 1) | ((l4 & 4) >> 1) | ((l4 & 8) >> 3);
    float raw = __shfl_sync(FULL, p[0], rev);
    float s = (lane < 16) ? (-raw * rtemp) : -CUDART_INF_F;

    int rank = 0;
#pragma unroll
    for (int m = 0; m < 16; m++) {
        float sm = __shfl_sync(FULL, s, m);
        rank += (sm > s || (sm == s && m < lane)) ? 1 : 0;
    }
    bool sel = rank < topk;
    unsigned bal = __ballot_sync(FULL, sel);

    float smax = sel ? s : -CUDART_INF_F;
#pragma unroll
    for (int o = 8; o > 0; o >>= 1)
        smax = fmaxf(smax, __shfl_xor_sync(FULL, smax, o));
    float e = sel ? expf(s - smax) : 0.f;
    float esum = e;
#pragma unroll
    for (int o = 8; o > 0; o >>= 1)
        esum += __shfl_xor_sync(FULL, esum, o);

    if (sel) {
        float w = e / esum;
        int k = __popc(bal & ((1u << lane) - 1u));
        size_t NT = (size_t)N * topk;
        size_t base = (size_t)i * topk + k;
        out[base]          = (float)i;
        out[NT + base]     = (float)mycol;
        out[2 * NT + base] = w;
    }
}

// ---------------------------------------------------------------------------
extern "C" void kernel_launch(void* const* d_in, const int* in_sizes, int n_in,
                              void* d_out, int out_size)
{
    const float* x    = (const float*)d_in[0];
    const int*   eidx = (const int*)  d_in[1];
    const float* W    = (const float*)d_in[2];
    const float* logd = (const float*)d_in[3];
    const float* logt = (const float*)d_in[4];

    const int D   = 128;
    const int N   = in_sizes[0] / D;
    const int deg = in_sizes[1] / (2 * N);
    const int topk = out_size / (3 * N);

    float* out = (float*)d_out;

    proj_kernel<<<(N + 127) / 128, 256>>>(x, W, logd, N);

    int warps_per_block = 256 / 32;
    int blocks = (N + warps_per_block - 1) / warps_per_block;
    edge_kernel<<<blocks, 256>>>(eidx, logt, out, N, deg, topk);
}

// round 7
// speedup vs baseline: 1.0342x; 1.0342x over previous
#include <cuda_runtime.h>
#include <math.h>
#include <math_constants.h>

#define D_DIM 128
#define MAXN  50048
#define EPS_F 1e-8f
#define FULL  0xffffffffu

// Scratch for the diag-scaled projection y = (x @ W^T) * sqrt(softplus(log_diag)+eps)
__device__ float g_xp[(size_t)MAXN * D_DIM];

// ---------------------------------------------------------------------------
// Kernel 1: projection GEMM, fp32 SIMT (at FFMA roofline), 128x128 block tile,
// 8x8 register micro-tile, K tiled by 32, sequential-k accumulation order
// (bitwise realization matters for the reference's top-k tie structure).
// ---------------------------------------------------------------------------
__global__ __launch_bounds__(256) void proj_kernel(
    const float* __restrict__ X, const float* __restrict__ W,
    const float* __restrict__ logd, int N)
{
    __shared__ float Xs[128 * 32];
    __shared__ float Wt[32 * 132];
    __shared__ float scale[128];

    const int tid  = threadIdx.x;
    const int row0 = blockIdx.x * 128;

    if (tid < 128) {
        float ld = logd[tid];
        float sp = (ld > 20.f) ? ld : log1pf(expf(ld));
        scale[tid] = sqrtf(sp + EPS_F);
    }

    float acc[8][8];
#pragma unroll
    for (int i = 0; i < 8; i++)
#pragma unroll
        for (int j = 0; j < 8; j++) acc[i][j] = 0.f;

    const int tx = tid & 15;
    const int ty = tid >> 4;
    const int lr = tid >> 3;
    const int lk = (tid & 7) * 4;

    for (int kt = 0; kt < 4; kt++) {
        __syncthreads();
#pragma unroll
        for (int it = 0; it < 4; it++) {
            int r  = lr + it * 32;
            int gr = row0 + r;
            float4 xv = make_float4(0.f, 0.f, 0.f, 0.f);
            if (gr < N) xv = *(const float4*)(X + (size_t)gr * D_DIM + kt * 32 + lk);
            *(float4*)(Xs + r * 32 + lk) = xv;
        }
#pragma unroll
        for (int it = 0; it < 4; it++) {
            int c = lr + it * 32;
            float4 wv = *(const float4*)(W + (size_t)c * D_DIM + kt * 32 + lk);
            Wt[(lk + 0) * 132 + c] = wv.x;
            Wt[(lk + 1) * 132 + c] = wv.y;
            Wt[(lk + 2) * 132 + c] = wv.z;
            Wt[(lk + 3) * 132 + c] = wv.w;
        }
        __syncthreads();

#pragma unroll 8
        for (int k = 0; k < 32; k++) {
            float xr[8];
#pragma unroll
            for (int i = 0; i < 8; i++) xr[i] = Xs[(ty * 8 + i) * 32 + k];
            float4 w0 = *(const float4*)(Wt + k * 132 + tx * 8);
            float4 w1 = *(const float4*)(Wt + k * 132 + tx * 8 + 4);
            float wc[8] = {w0.x, w0.y, w0.z, w0.w, w1.x, w1.y, w1.z, w1.w};
#pragma unroll
            for (int i = 0; i < 8; i++)
#pragma unroll
                for (int j = 0; j < 8; j++)
                    acc[i][j] = fmaf(xr[i], wc[j], acc[i][j]);
        }
    }

#pragma unroll
    for (int i = 0; i < 8; i++) {
        int gr = row0 + ty * 8 + i;
        if (gr < N) {
#pragma unroll
            for (int j = 0; j < 8; j += 4) {
                float4 o;
                o.x = acc[i][j + 0] * scale[tx * 8 + j + 0];
                o.y = acc[i][j + 1] * scale[tx * 8 + j + 1];
                o.z = acc[i][j + 2] * scale[tx * 8 + j + 2];
                o.w = acc[i][j + 3] * scale[tx * 8 + j + 3];
                *(float4*)(g_xp + (size_t)gr * D_DIM + tx * 8 + j) = o;
            }
        }
    }
}

// ---------------------------------------------------------------------------
// Kernel 2: one warp per node. Gathers in 4 batches of 4 (reg-lean -> 62.5%
// occupancy); per-neighbor score math and butterfly reduction bitwise
// identical to the R2 passing version.
// ---------------------------------------------------------------------------
__global__ __launch_bounds__(256, 5) void edge_kernel(
    const int* __restrict__ eidx, const float* __restrict__ logt,
    float* __restrict__ out, int N, int deg, int topk)
{
    const int warp = blockIdx.x * (blockDim.x >> 5) + (threadIdx.x >> 5);
    const int lane = threadIdx.x & 31;
    if (warp >= N) return;
    const int i = warp;

    const int* colp = eidx + (size_t)N * deg + (size_t)i * deg;
    int mycol = (lane < 16) ? colp[lane] : 0;

    float4 yi = *(const float4*)(g_xp + (size_t)i * D_DIM + lane * 4);
    const float rtemp = expf(-logt[0]);

    // partial squared distances, gathered in 4 batches of 4 rows
    float p[16];
#pragma unroll
    for (int g = 0; g < 4; g++) {
        float4 v[4];
#pragma unroll
        for (int n = 0; n < 4; n++) {
            int c = __shfl_sync(FULL, mycol, g * 4 + n);
            v[n] = *(const float4*)(g_xp + (size_t)c * D_DIM + lane * 4);
        }
#pragma unroll
        for (int n = 0; n < 4; n++) {
            float dx = yi.x - v[n].x;
            float dy = yi.y - v[n].y;
            float dz = yi.z - v[n].z;
            float dw = yi.w - v[n].w;
            p[g * 4 + n] = dx * dx + dy * dy + dz * dz + dw * dw;
        }
    }

    // Butterfly transpose-reduce (identical to R2)
    {
        const bool b0 = lane & 1;
#pragma unroll
        for (int k = 0; k < 8; k++) {
            float send = b0 ? p[k] : p[k + 8];
            float recv = __shfl_xor_sync(FULL, send, 1);
            p[k] = (b0 ? p[k + 8] : p[k]) + recv;
        }
        const bool b1 = lane & 2;
#pragma unroll
        for (int k = 0; k < 4; k++) {
            float send = b1 ? p[k] : p[k + 4];
            float recv = __shfl_xor_sync(FULL, send, 2);
            p[k] = (b1 ? p[k + 4] : p[k]) + recv;
        }
        const bool b2 = lane & 4;
#pragma unroll
        for (int k = 0; k < 2; k++) {
            float send = b2 ? p[k] : p[k + 2];
            float recv = __shfl_xor_sync(FULL, send, 4);
            p[k] = (b2 ? p[k + 2] : p[k]) + recv;
        }
        const bool b3 = lane & 8;
        {
            float send = b3 ? p[0] : p[1];
            float recv = __shfl_xor_sync(FULL, send, 8);
            p[0] = (b3 ? p[1] : p[0]) + recv;
        }
        p[0] += __shfl_xor_sync(FULL, p[0], 16);
    }

    const int l4  = lane & 15;
    const int rev = ((l4 & 1) << 3) | ((l4 & 2) << 1) | ((l4 & 4) >> 1) | ((l4 & 8) >> 3);
    float raw = __shfl_sync(FULL, p[0], rev);
    float s = (lane < 16) ? (-raw * rtemp) : -CUDART_INF_F;

    // stable rank (lax.top_k semantics: ties -> lower index)
    int rank = 0;
#pragma unroll
    for (int m = 0; m < 16; m++) {
        float sm = __shfl_sync(FULL, s, m);
        rank += (sm > s || (sm == s && m < lane)) ? 1 : 0;
    }
    bool sel = rank < topk;
    unsigned bal = __ballot_sync(FULL, sel);

    float smax = sel ? s : -CUDART_INF_F;
#pragma unroll
    for (int o = 8; o > 0; o >>= 1)
        smax = fmaxf(smax, __shfl_xor_sync(FULL, smax, o));
    float e = sel ? expf(s - smax) : 0.f;
    float esum = e;
#pragma unroll
    for (int o = 8; o > 0; o >>= 1)
        esum += __shfl_xor_sync(FULL, esum, o);

    if (sel) {
        float w = e / esum;
        int k = __popc(bal & ((1u << lane) - 1u));
        size_t NT = (size_t)N * topk;
        size_t base = (size_t)i * topk + k;
        out[base]          = (float)i;
        out[NT + base]     = (float)mycol;
        out[2 * NT + base] = w;
    }
}

// ---------------------------------------------------------------------------
extern "C" void kernel_launch(void* const* d_in, const int* in_sizes, int n_in,
                              void* d_out, int out_size)
{
    const float* x    = (const float*)d_in[0];
    const int*   eidx = (const int*)  d_in[1];
    const float* W    = (const float*)d_in[2];
    const float* logd = (const float*)d_in[3];
    const float* logt = (const float*)d_in[4];

    const int D   = 128;
    const int N   = in_sizes[0] / D;
    const int deg = in_sizes[1] / (2 * N);
    const int topk = out_size / (3 * N);

    float* out = (float*)d_out;

    proj_kernel<<<(N + 127) / 128, 256>>>(x, W, logd, N);

    int warps_per_block = 256 / 32;
    int blocks = (N + warps_per_block - 1) / warps_per_block;
    edge_kernel<<<blocks, 256>>>(eidx, logt, out, N, deg, topk);
}